// round 16
// baseline (speedup 1.0000x reference)
#include <cuda_runtime.h>
#include <math.h>

#define C_IN   64
#define V_N    2048
#define Q_N    512
#define BT_N   8
#define KSEL   103
#define JW     33
#define M_TOT  2112          // 64 * 33
#define NSPLIT 11            // gB m-splits (192 m each)
#define G2ST   64            // dup-g row stride (floats): 32 j-pairs

typedef unsigned long long ull;

// ---- scratch (static device globals; no runtime allocation) ----
__device__ float d_xl [BT_N * V_N * C_IN];
__device__ float d_g2 [Q_N * KSEL * G2ST];     // g duplicated pairs: [q][k][j*2(+1)]
__device__ float d_wq [Q_N * KSEL];            // softmax weights
__device__ int   d_ind[Q_N * KSEL];
__device__ float d_A  [BT_N * Q_N * M_TOT];    // layout: [row][j*64 + c]
__device__ float d_W2e[M_TOT * 32];            // [j*64+c][d]
__device__ float d_part[NSPLIT * BT_N * Q_N * 32];  // gB partial sums

// ---- f32x2 packed math ----
__device__ __forceinline__ ull fma2v(ull a, ull b, ull c) {
    ull d; asm("fma.rn.f32x2 %0, %1, %2, %3;" : "=l"(d) : "l"(a), "l"(b), "l"(c)); return d;
}
__device__ __forceinline__ ull pack2(float lo, float hi) {
    ull r; asm("mov.b64 %0, {%1, %2};" : "=l"(r) : "f"(lo), "f"(hi)); return r;
}
__device__ __forceinline__ float2 unpack2(ull v) {
    float2 r; asm("mov.b64 {%0, %1}, %2;" : "=f"(r.x), "=f"(r.y) : "l"(v)); return r;
}
__device__ __forceinline__ float wrap01(float d) {
    float t = d + 0.5f; t -= floorf(t); return t - 0.5f;
}

// ============================================================
// K_w2e
// ============================================================
__global__ void k_w2e(const float* __restrict__ W2, const float* __restrict__ filt) {
    int idx = blockIdx.x * 256 + threadIdx.x;
    if (idx < M_TOT * 32) {
        int m = idx >> 5, dd = idx & 31;
        int j = m >> 6, c = m & 63;
        d_W2e[idx] = (j < 32) ? __ldg(&W2[(c * 32 + dd) * 32 + j]) : __ldg(&filt[c * 32 + dd]);
    }
}

// ============================================================
// K0: xl = x @ W_lin^T + b
// ============================================================
__global__ void __launch_bounds__(256) k_xlin(const float* __restrict__ x,
                                              const float* __restrict__ Wl,
                                              const float* __restrict__ bl) {
    __shared__ __align__(16) float xs[512];
    __shared__ __align__(16) float ws[64 * 66];
    int tid = threadIdx.x;
    int base = blockIdx.x * 512;
    xs[tid]       = x[base + tid];
    xs[tid + 256] = x[base + 256 + tid];
    for (int i = tid; i < 4096; i += 256) { int cc = i >> 6, ii = i & 63; ws[cc * 66 + ii] = Wl[i]; }
    __syncthreads();
    int c = tid & 63, rp = tid >> 6;
    ull aA = 0, aB = 0;
    const ull* wp = (const ull*)&ws[c * 66];
    const ull* xA = (const ull*)&xs[rp * 64];
    const ull* xB = (const ull*)&xs[(rp + 4) * 64];
#pragma unroll
    for (int i2 = 0; i2 < 32; i2++) {
        ull w2_ = wp[i2];
        aA = fma2v(xA[i2], w2_, aA);
        aB = fma2v(xB[i2], w2_, aB);
    }
    float bv = __ldg(&bl[c]);
    float2 fA = unpack2(aA), fB = unpack2(aB);
    d_xl[base + rp * 64 + c]       = fA.x + fA.y + bv;
    d_xl[base + (rp + 4) * 64 + c] = fB.x + fB.y + bv;
}

// ============================================================
// K1: per query — radix-select 103 NN (candidate compaction),
// softmax weights, RFF/MLP/GELU -> duplicated g2 + w
// ============================================================
__global__ void __launch_bounds__(256) k_select(const float* __restrict__ pos,
                                                const float* __restrict__ qpos,
                                                const float* __restrict__ Bmat,
                                                const float* __restrict__ W1,
                                                const float* __restrict__ b1) {
    __shared__ float e_s[V_N];
    __shared__ float cnd[V_N];
    __shared__ unsigned hist[256];
    __shared__ int   sel_i[KSEL];
    __shared__ float sel_e[KSEL];
    __shared__ float sel_w[KSEL];
    __shared__ __align__(16) float kf_s[KSEL * 32];
    __shared__ float bs[32];
    __shared__ unsigned s_kth;
    __shared__ int s_rem, s_ncand;
    __shared__ float s_min, s_sum;
    __shared__ int w_lt[8], w_eq[8], w_lt_off[8], w_eq_off[8];

    int q = blockIdx.x, tid = threadIdx.x, wid = tid >> 5, lane = tid & 31;
    const unsigned full = 0xffffffffu;
    unsigned ltm = (1u << lane) - 1u;
    float q0 = __ldg(&qpos[2 * q]), q1 = __ldg(&qpos[2 * q + 1]);

    ull wl[16];
#pragma unroll
    for (int t = 0; t < 16; t++) wl[t] = *(const ull*)&W1[lane * 32 + 2 * t];
    float b1r = __ldg(&b1[lane]);
    if (tid < 32) bs[tid] = __ldg(&Bmat[tid]);
    if (tid == 0) s_ncand = 0;

    for (int v = tid; v < V_N; v += 256) {
        float d0 = wrap01(q0 - __ldg(&pos[2 * v]));
        float d1 = wrap01(q1 - __ldg(&pos[2 * v + 1]));
        e_s[v] = d0 * d0 + d1 * d1;
    }
    hist[tid] = 0;
    __syncthreads();

    // ---- pass 1 over all 2048 (byte 3) ----
    for (int v = tid; v < V_N; v += 256)
        atomicAdd(&hist[__float_as_uint(e_s[v]) >> 24], 1u);
    __syncthreads();
    if (tid < 32) {
        unsigned c8[8]; int lsum = 0;
#pragma unroll
        for (int j = 0; j < 8; j++) { c8[j] = hist[tid * 8 + j]; lsum += (int)c8[j]; }
        int pre = lsum;
#pragma unroll
        for (int o = 1; o < 32; o <<= 1) { int t2 = __shfl_up_sync(full, pre, o); if (lane >= o) pre += t2; }
        int excl = pre - lsum;
        if (excl < KSEL && pre >= KSEL) {
            int r2 = KSEL - excl; int cum = 0, j = 0;
#pragma unroll
            for (j = 0; j < 8; j++) { cum += (int)c8[j]; if (cum >= r2) break; }
            s_kth = ((unsigned)(tid * 8 + j)) << 24;
            s_rem = r2 - (cum - (int)c8[j]);
        }
    }
    __syncthreads();
    unsigned prefix = s_kth; int remaining = s_rem;
    unsigned b1top = prefix >> 24;
    for (int v = tid; v < V_N; v += 256) {
        unsigned u = __float_as_uint(e_s[v]);
        if ((u >> 24) == b1top) { int p = atomicAdd(&s_ncand, 1); cnd[p] = e_s[v]; }
    }
    __syncthreads();
    int ncand = s_ncand;

    // ---- passes 2-4 over candidates only ----
    for (int shift = 16; shift >= 0; shift -= 8) {
        hist[tid] = 0;
        __syncthreads();
        unsigned pm = 0xFFFFFFFFu << (shift + 8);
        for (int i = tid; i < ncand; i += 256) {
            unsigned u = __float_as_uint(cnd[i]);
            if ((u & pm) == prefix) atomicAdd(&hist[(u >> shift) & 255], 1u);
        }
        __syncthreads();
        if (tid < 32) {
            unsigned c8[8]; int lsum = 0;
#pragma unroll
            for (int j = 0; j < 8; j++) { c8[j] = hist[tid * 8 + j]; lsum += (int)c8[j]; }
            int pre = lsum;
#pragma unroll
            for (int o = 1; o < 32; o <<= 1) { int t2 = __shfl_up_sync(full, pre, o); if (lane >= o) pre += t2; }
            int excl = pre - lsum;
            if (excl < remaining && pre >= remaining) {
                int r2 = remaining - excl; int cum = 0, j = 0;
#pragma unroll
                for (j = 0; j < 8; j++) { cum += (int)c8[j]; if (cum >= r2) break; }
                s_kth = prefix | ((unsigned)(tid * 8 + j) << shift);
                s_rem = r2 - (cum - (int)c8[j]);
            }
        }
        __syncthreads();
        prefix = s_kth; remaining = s_rem;
        __syncthreads();
    }
    unsigned kth = prefix;

    // ---- parallel collection across 8 warps (tie-break: ascending index) ----
    {
        int nlt = 0, neq = 0;
#pragma unroll
        for (int it = 0; it < 8; it++) {
            unsigned u = __float_as_uint(e_s[wid * 256 + it * 32 + lane]);
            nlt += __popc(__ballot_sync(full, u < kth));
            neq += __popc(__ballot_sync(full, u == kth));
        }
        if (lane == 0) { w_lt[wid] = nlt; w_eq[wid] = neq; }
        __syncthreads();
        if (tid == 0) {
            int a = 0;
            for (int w = 0; w < 8; w++) { w_lt_off[w] = a; a += w_lt[w]; }
            int b2 = a;
            for (int w = 0; w < 8; w++) { w_eq_off[w] = b2; b2 += w_eq[w]; }
        }
        __syncthreads();
        int plt = w_lt_off[wid], peq = w_eq_off[wid];
#pragma unroll
        for (int it = 0; it < 8; it++) {
            int v = wid * 256 + it * 32 + lane;
            unsigned u = __float_as_uint(e_s[v]);
            bool lt = u < kth; unsigned bal = __ballot_sync(full, lt);
            if (lt) { int p = plt + __popc(bal & ltm); sel_i[p] = v; sel_e[p] = e_s[v]; }
            plt += __popc(bal);
            bool eq = (u == kth); unsigned b3 = __ballot_sync(full, eq);
            if (eq) { int p = peq + __popc(b3 & ltm); if (p < KSEL) { sel_i[p] = v; sel_e[p] = e_s[v]; } }
            peq += __popc(b3);
        }
    }
    __syncthreads();

    if (tid < 32) {
        float m = 3.0e38f;
        for (int k = lane; k < KSEL; k += 32) m = fminf(m, sel_e[k]);
        for (int o = 16; o; o >>= 1) m = fminf(m, __shfl_xor_sync(full, m, o));
        if (lane == 0) s_min = m;
    }
    __syncthreads();
    float emin = s_min;
    float emax = __uint_as_float(kth);
    float denom = (emax - emin) + 1e-8f;
    if (tid < KSEL) sel_w[tid] = expf(-((sel_e[tid] - emin) / denom));
    __syncthreads();
    if (tid < 32) {
        float s = 0.f;
        for (int k = lane; k < KSEL; k += 32) s += sel_w[k];
        for (int o = 16; o; o >>= 1) s += __shfl_xor_sync(full, s, o);
        if (lane == 0) s_sum = s;
    }
    __syncthreads();

    if (tid < KSEL) {
        float w = sel_w[tid] / s_sum;
        sel_w[tid] = w;
        int v = sel_i[tid];
        float d0 = wrap01(q0 - __ldg(&pos[2 * v]));
        float d1 = wrap01(q1 - __ldg(&pos[2 * v + 1]));
#pragma unroll
        for (int j = 0; j < 16; j++) {
            float p = 6.283185307179586f * (d0 * bs[j] + d1 * bs[16 + j]);
            float sv, cv; __sincosf(p, &sv, &cv);
            kf_s[tid * 32 + j]      = sv;
            kf_s[tid * 32 + 16 + j] = cv;
        }
        d_wq[q * KSEL + tid] = w;
        d_ind[q * KSEL + tid] = v;
    }
    __syncthreads();

    // ---- MLP -> GELU -> duplicated-pair writeout ----
#pragma unroll 1
    for (int rr = 0; rr < 13; rr++) {
        int k = wid + rr * 8;
        if (k < KSEL) {
            ull acc = 0;
            const ull* kp = (const ull*)&kf_s[k * 32];
#pragma unroll
            for (int t = 0; t < 16; t++) acc = fma2v(kp[t], wl[t], acc);
            float2 f = unpack2(acc);
            float a = f.x + f.y + b1r;
            float h = 0.5f * a * (1.0f + erff(a * 0.70710678118654752f));
            float gw = sel_w[k] * h;
            *(float2*)&d_g2[(q * KSEL + k) * G2ST + lane * 2] = make_float2(gw, gw);
        }
    }
}

// ============================================================
// K2a: block = (q, bt), 256 threads, 2-way k-split, thread tile 4c x 4j.
// g pre-duplicated in gmem/smem: FFMA2 second operand comes straight from
// LDS.128 (no pack MOVs). 52.7 KB dyn smem -> 4 blocks/SM.
// ============================================================
#define GA_SMEM ((KSEL * G2ST + KSEL * C_IN) * 4)   // 52736 B

__global__ void __launch_bounds__(256) k_gA() {
    extern __shared__ __align__(16) float sm[];
    float* g_s = sm;                  // [103][64] dup pairs
    float* xg  = sm + KSEL * G2ST;    // [103][64]; tail reused as reduction buf
    __shared__ int ind_s[KSEL];
    __shared__ float w_s[KSEL];
    __shared__ float wred[8][C_IN];

    int bx = blockIdx.x, q = bx >> 3, bt = bx & 7;
    int tid = threadIdx.x;

    if (tid < KSEL) { ind_s[tid] = d_ind[q * KSEL + tid]; w_s[tid] = d_wq[q * KSEL + tid]; }
    {
        const float4* gsrc = (const float4*)&d_g2[q * KSEL * G2ST];
        float4* gdst = (float4*)g_s;
        for (int i = tid; i < KSEL * G2ST / 4; i += 256) gdst[i] = gsrc[i];
    }
    __syncthreads();

    // gather: warp w loads rows w, w+8, ...; float2 per lane; w-column on the fly
    {
        int w = tid >> 5, lane = tid & 31;
        const float* xb = &d_xl[bt * V_N * C_IN];
        float2 wa = make_float2(0.f, 0.f);
        for (int r = w; r < KSEL; r += 8) {
            float2 v = __ldg((const float2*)&xb[ind_s[r] * C_IN + lane * 2]);
            *(float2*)&xg[r * C_IN + lane * 2] = v;
            float wr = w_s[r];
            wa.x += wr * v.x; wa.y += wr * v.y;
        }
        wred[w][lane * 2]     = wa.x;
        wred[w][lane * 2 + 1] = wa.y;
    }
    __syncthreads();

    int kh = tid >> 7;                 // k-half: 0 -> [0,52), 1 -> [52,103)
    int t  = tid & 127;
    int cg = t & 15, jg = t >> 4;      // 16 c-groups of 4; 8 j-groups of 4
    const float* xgp = &xg[cg * 4];
    const float* gsp = &g_s[jg * 8];   // 4 dup pairs = 32B, 16B-aligned
    int kbeg = kh ? 52 : 0;
    int kend = kh ? KSEL : 52;

    ull acc[4][2];
#pragma unroll
    for (int a = 0; a < 4; a++) { acc[a][0] = 0; acc[a][1] = 0; }

#pragma unroll 2
    for (int k = kbeg; k < kend; k++) {
        ulonglong2 x0 = *(const ulonglong2*)&xgp[k * C_IN];
        ulonglong2 ga = *(const ulonglong2*)&gsp[k * G2ST];
        ulonglong2 gb = *(const ulonglong2*)&gsp[k * G2ST + 4];
        acc[0][0] = fma2v(x0.x, ga.x, acc[0][0]); acc[0][1] = fma2v(x0.y, ga.x, acc[0][1]);
        acc[1][0] = fma2v(x0.x, ga.y, acc[1][0]); acc[1][1] = fma2v(x0.y, ga.y, acc[1][1]);
        acc[2][0] = fma2v(x0.x, gb.x, acc[2][0]); acc[2][1] = fma2v(x0.y, gb.x, acc[2][1]);
        acc[3][0] = fma2v(x0.x, gb.y, acc[3][0]); acc[3][1] = fma2v(x0.y, gb.y, acc[3][1]);
    }

    __syncthreads();
    float* red = xg;                   // [128][20] (80B stride, 16B-aligned)
    if (kh == 1) {
        float* rp = &red[t * 20];
#pragma unroll
        for (int j2 = 0; j2 < 4; j2++)
            *(ulonglong2*)&rp[j2 * 4] = make_ulonglong2(acc[j2][0], acc[j2][1]);
    }
    __syncthreads();
    if (kh == 0) {
        const float* rp = &red[t * 20];
        int row = bt * Q_N + q;
        float* Ar = &d_A[row * M_TOT];
#pragma unroll
        for (int j2 = 0; j2 < 4; j2++) {
            float2 f0 = unpack2(acc[j2][0]), f1 = unpack2(acc[j2][1]);
            float4 p = *(const float4*)&rp[j2 * 4];
            *(float4*)&Ar[(jg * 4 + j2) * C_IN + cg * 4] =
                make_float4(f0.x + p.x, f0.y + p.y, f1.x + p.z, f1.y + p.w);
        }
        if (t < C_IN) {
            float a0 = 0.f;
#pragma unroll
            for (int rr = 0; rr < 8; rr++) a0 += wred[rr][t];
            Ar[32 * C_IN + t] = a0;
        }
    }
}

// ============================================================
// K2b: register-blocked GEMM on transposed A tile.
// grid = 64 row-tiles x 11 m-splits = 704 blocks (~4.8/SM).
// ============================================================
#define AST 66      // As_t row stride (even -> 8B-aligned pairs)

__global__ void __launch_bounds__(256) k_gB1() {
    __shared__ __align__(16) float As[64 * AST];   // [m][row] 16.9KB
    __shared__ __align__(16) float Wt[64 * 32];    // [m][d]    8KB
    int bx = blockIdx.x;
    int rt = bx & 63, ms = bx >> 6;                // 704 blocks = 11 x 64
    int tid = threadIdx.x;
    int rp = tid >> 3, dq = tid & 7;               // 32 row-pairs x 8 d-quads
    int r0 = rt * 64;
    int mbase0 = ms * 192;

    ull acc[4] = {0, 0, 0, 0};

    for (int st = 0; st < 3; st++) {
        int mb = mbase0 + st * 64;
        for (int i = tid; i < 4096; i += 256) {
            int row = i >> 6, m = i & 63;
            As[m * AST + row] = d_A[(r0 + row) * M_TOT + mb + m];
        }
        const float* wsrc = &d_W2e[mb * 32];
        for (int i = tid; i < 2048; i += 256) Wt[i] = wsrc[i];
        __syncthreads();

        const float* ap = &As[rp * 2];
        const float* wp = &Wt[dq * 4];
#pragma unroll 4
        for (int m = 0; m < 64; m++) {
            ull a = *(const ull*)&ap[m * AST];
            float4 w4 = *(const float4*)&wp[m * 32];
            acc[0] = fma2v(a, pack2(w4.x, w4.x), acc[0]);
            acc[1] = fma2v(a, pack2(w4.y, w4.y), acc[1]);
            acc[2] = fma2v(a, pack2(w4.z, w4.z), acc[2]);
            acc[3] = fma2v(a, pack2(w4.w, w4.w), acc[3]);
        }
        __syncthreads();
    }

    int row0 = r0 + rp * 2;
    float* pp = &d_part[(ms * 4096 + row0) * 32 + dq * 4];
#pragma unroll
    for (int j = 0; j < 4; j++) {
        float2 f = unpack2(acc[j]);
        pp[j]      = f.x;
        pp[32 + j] = f.y;
    }
}

__global__ void k_gB2(const float* __restrict__ bias, float* __restrict__ out) {
    int i = blockIdx.x * 256 + threadIdx.x;        // 131072 outputs
    if (i < BT_N * Q_N * 32) {
        float s = __ldg(&bias[i & 31]);
#pragma unroll
        for (int ms = 0; ms < NSPLIT; ms++)
            s += d_part[ms * 131072 + i];
        out[i] = s;
    }
}

// ============================================================
extern "C" void kernel_launch(void* const* d_in, const int* in_sizes, int n_in,
                              void* d_out, int out_size) {
    const float* x    = (const float*)d_in[0];
    const float* pos  = (const float*)d_in[1];
    const float* qpos = (const float*)d_in[2];
    const float* Wl   = (const float*)d_in[3];
    const float* bl   = (const float*)d_in[4];
    const float* Bm   = (const float*)d_in[5];
    const float* W1   = (const float*)d_in[6];
    const float* b1   = (const float*)d_in[7];
    const float* W2   = (const float*)d_in[8];
    const float* filt = (const float*)d_in[9];
    const float* bias = (const float*)d_in[10];
    float* out = (float*)d_out;

    static cudaStream_t s1 = nullptr;
    static cudaEvent_t evRoot = nullptr, evJoin = nullptr;
    if (!s1) {
        cudaStreamCreateWithFlags(&s1, cudaStreamNonBlocking);
        cudaEventCreateWithFlags(&evRoot, cudaEventDisableTiming);
        cudaEventCreateWithFlags(&evJoin, cudaEventDisableTiming);
        cudaFuncSetAttribute(k_gA, cudaFuncAttributeMaxDynamicSharedMemorySize, GA_SMEM);
    }

    // fork: k_xlin + k_w2e on side stream, k_select on main stream
    cudaEventRecord(evRoot, 0);
    cudaStreamWaitEvent(s1, evRoot, 0);

    k_select<<<Q_N, 256>>>(pos, qpos, Bm, W1, b1);
    k_xlin <<<2048, 256, 0, s1>>>(x, Wl, bl);
    k_w2e  <<<264, 256, 0, s1>>>(W2, filt);

    cudaEventRecord(evJoin, s1);
    cudaStreamWaitEvent(0, evJoin, 0);

    k_gA  <<<Q_N * BT_N, 256, GA_SMEM>>>();
    k_gB1 <<<64 * NSPLIT, 256>>>();
    k_gB2 <<<512, 256>>>(bias, out);
}

// round 17
// speedup vs baseline: 1.0546x; 1.0546x over previous
#include <cuda_runtime.h>
#include <math.h>

#define C_IN   64
#define V_N    2048
#define Q_N    512
#define BT_N   8
#define KSEL   103
#define JW     33
#define M_TOT  2112          // 64 * 33
#define GST    36            // padded g row stride
#define NSPLIT 11            // gB m-splits (192 m each)

typedef unsigned long long ull;

// ---- scratch (static device globals; no runtime allocation) ----
__device__ float d_xl [BT_N * V_N * C_IN];
__device__ float d_g  [Q_N * KSEL * JW];
__device__ int   d_ind[Q_N * KSEL];
__device__ float d_A  [BT_N * Q_N * M_TOT];    // layout: [row][j*64 + c]
__device__ float d_W2e[M_TOT * 32];            // [j*64+c][d]
__device__ float d_part[NSPLIT * BT_N * Q_N * 32];  // gB partial sums

// ---- f32x2 packed math ----
__device__ __forceinline__ ull fma2v(ull a, ull b, ull c) {
    ull d; asm("fma.rn.f32x2 %0, %1, %2, %3;" : "=l"(d) : "l"(a), "l"(b), "l"(c)); return d;
}
__device__ __forceinline__ ull pack2(float lo, float hi) {
    ull r; asm("mov.b64 %0, {%1, %2};" : "=l"(r) : "f"(lo), "f"(hi)); return r;
}
__device__ __forceinline__ float2 unpack2(ull v) {
    float2 r; asm("mov.b64 {%0, %1}, %2;" : "=f"(r.x), "=f"(r.y) : "l"(v)); return r;
}
__device__ __forceinline__ float wrap01(float d) {
    float t = d + 0.5f; t -= floorf(t); return t - 0.5f;
}

// ============================================================
// K_w2e
// ============================================================
__global__ void k_w2e(const float* __restrict__ W2, const float* __restrict__ filt) {
    int idx = blockIdx.x * 256 + threadIdx.x;
    if (idx < M_TOT * 32) {
        int m = idx >> 5, dd = idx & 31;
        int j = m >> 6, c = m & 63;
        d_W2e[idx] = (j < 32) ? __ldg(&W2[(c * 32 + dd) * 32 + j]) : __ldg(&filt[c * 32 + dd]);
    }
}

// ============================================================
// K0: xl = x @ W_lin^T + b
// ============================================================
__global__ void __launch_bounds__(256) k_xlin(const float* __restrict__ x,
                                              const float* __restrict__ Wl,
                                              const float* __restrict__ bl) {
    __shared__ __align__(16) float xs[512];
    __shared__ __align__(16) float ws[64 * 66];
    int tid = threadIdx.x;
    int base = blockIdx.x * 512;
    xs[tid]       = x[base + tid];
    xs[tid + 256] = x[base + 256 + tid];
    for (int i = tid; i < 4096; i += 256) { int cc = i >> 6, ii = i & 63; ws[cc * 66 + ii] = Wl[i]; }
    __syncthreads();
    int c = tid & 63, rp = tid >> 6;
    ull aA = 0, aB = 0;
    const ull* wp = (const ull*)&ws[c * 66];
    const ull* xA = (const ull*)&xs[rp * 64];
    const ull* xB = (const ull*)&xs[(rp + 4) * 64];
#pragma unroll
    for (int i2 = 0; i2 < 32; i2++) {
        ull w2_ = wp[i2];
        aA = fma2v(xA[i2], w2_, aA);
        aB = fma2v(xB[i2], w2_, aB);
    }
    float bv = __ldg(&bl[c]);
    float2 fA = unpack2(aA), fB = unpack2(aB);
    d_xl[base + rp * 64 + c]       = fA.x + fA.y + bv;
    d_xl[base + (rp + 4) * 64 + c] = fB.x + fB.y + bv;
}

// ============================================================
// K1: per query — radix-select 103 NN (candidate compaction),
// softmax weights, RFF/MLP/GELU -> g. qbase selects the query chunk.
// ============================================================
__global__ void __launch_bounds__(256) k_select(const float* __restrict__ pos,
                                                const float* __restrict__ qpos,
                                                const float* __restrict__ Bmat,
                                                const float* __restrict__ W1,
                                                const float* __restrict__ b1,
                                                int qbase) {
    __shared__ float e_s[V_N];
    __shared__ float cnd[V_N];
    __shared__ unsigned hist[256];
    __shared__ int   sel_i[KSEL];
    __shared__ float sel_e[KSEL];
    __shared__ float sel_w[KSEL];
    __shared__ __align__(16) float kf_s[KSEL * 32];
    __shared__ float bs[32];
    __shared__ unsigned s_kth;
    __shared__ int s_rem, s_ncand;
    __shared__ float s_min, s_sum;
    __shared__ int w_lt[8], w_eq[8], w_lt_off[8], w_eq_off[8];

    int q = qbase + blockIdx.x, tid = threadIdx.x, wid = tid >> 5, lane = tid & 31;
    const unsigned full = 0xffffffffu;
    unsigned ltm = (1u << lane) - 1u;
    float q0 = __ldg(&qpos[2 * q]), q1 = __ldg(&qpos[2 * q + 1]);

    ull wl[16];
#pragma unroll
    for (int t = 0; t < 16; t++) wl[t] = *(const ull*)&W1[lane * 32 + 2 * t];
    float b1r = __ldg(&b1[lane]);
    if (tid < 32) bs[tid] = __ldg(&Bmat[tid]);
    if (tid == 0) s_ncand = 0;

    for (int v = tid; v < V_N; v += 256) {
        float d0 = wrap01(q0 - __ldg(&pos[2 * v]));
        float d1 = wrap01(q1 - __ldg(&pos[2 * v + 1]));
        e_s[v] = d0 * d0 + d1 * d1;
    }
    hist[tid] = 0;
    __syncthreads();

    // ---- pass 1 over all 2048 (byte 3) ----
    for (int v = tid; v < V_N; v += 256)
        atomicAdd(&hist[__float_as_uint(e_s[v]) >> 24], 1u);
    __syncthreads();
    if (tid < 32) {
        unsigned c8[8]; int lsum = 0;
#pragma unroll
        for (int j = 0; j < 8; j++) { c8[j] = hist[tid * 8 + j]; lsum += (int)c8[j]; }
        int pre = lsum;
#pragma unroll
        for (int o = 1; o < 32; o <<= 1) { int t2 = __shfl_up_sync(full, pre, o); if (lane >= o) pre += t2; }
        int excl = pre - lsum;
        if (excl < KSEL && pre >= KSEL) {
            int r2 = KSEL - excl; int cum = 0, j = 0;
#pragma unroll
            for (j = 0; j < 8; j++) { cum += (int)c8[j]; if (cum >= r2) break; }
            s_kth = ((unsigned)(tid * 8 + j)) << 24;
            s_rem = r2 - (cum - (int)c8[j]);
        }
    }
    __syncthreads();
    unsigned prefix = s_kth; int remaining = s_rem;
    unsigned b1top = prefix >> 24;
    for (int v = tid; v < V_N; v += 256) {
        unsigned u = __float_as_uint(e_s[v]);
        if ((u >> 24) == b1top) { int p = atomicAdd(&s_ncand, 1); cnd[p] = e_s[v]; }
    }
    __syncthreads();
    int ncand = s_ncand;

    // ---- passes 2-4 over candidates only ----
    for (int shift = 16; shift >= 0; shift -= 8) {
        hist[tid] = 0;
        __syncthreads();
        unsigned pm = 0xFFFFFFFFu << (shift + 8);
        for (int i = tid; i < ncand; i += 256) {
            unsigned u = __float_as_uint(cnd[i]);
            if ((u & pm) == prefix) atomicAdd(&hist[(u >> shift) & 255], 1u);
        }
        __syncthreads();
        if (tid < 32) {
            unsigned c8[8]; int lsum = 0;
#pragma unroll
            for (int j = 0; j < 8; j++) { c8[j] = hist[tid * 8 + j]; lsum += (int)c8[j]; }
            int pre = lsum;
#pragma unroll
            for (int o = 1; o < 32; o <<= 1) { int t2 = __shfl_up_sync(full, pre, o); if (lane >= o) pre += t2; }
            int excl = pre - lsum;
            if (excl < remaining && pre >= remaining) {
                int r2 = remaining - excl; int cum = 0, j = 0;
#pragma unroll
                for (j = 0; j < 8; j++) { cum += (int)c8[j]; if (cum >= r2) break; }
                s_kth = prefix | ((unsigned)(tid * 8 + j) << shift);
                s_rem = r2 - (cum - (int)c8[j]);
            }
        }
        __syncthreads();
        prefix = s_kth; remaining = s_rem;
        __syncthreads();
    }
    unsigned kth = prefix;

    // ---- parallel collection across 8 warps (tie-break: ascending index) ----
    {
        int nlt = 0, neq = 0;
#pragma unroll
        for (int it = 0; it < 8; it++) {
            unsigned u = __float_as_uint(e_s[wid * 256 + it * 32 + lane]);
            nlt += __popc(__ballot_sync(full, u < kth));
            neq += __popc(__ballot_sync(full, u == kth));
        }
        if (lane == 0) { w_lt[wid] = nlt; w_eq[wid] = neq; }
        __syncthreads();
        if (tid == 0) {
            int a = 0;
            for (int w = 0; w < 8; w++) { w_lt_off[w] = a; a += w_lt[w]; }
            int b2 = a;
            for (int w = 0; w < 8; w++) { w_eq_off[w] = b2; b2 += w_eq[w]; }
        }
        __syncthreads();
        int plt = w_lt_off[wid], peq = w_eq_off[wid];
#pragma unroll
        for (int it = 0; it < 8; it++) {
            int v = wid * 256 + it * 32 + lane;
            unsigned u = __float_as_uint(e_s[v]);
            bool lt = u < kth; unsigned bal = __ballot_sync(full, lt);
            if (lt) { int p = plt + __popc(bal & ltm); sel_i[p] = v; sel_e[p] = e_s[v]; }
            plt += __popc(bal);
            bool eq = (u == kth); unsigned b3 = __ballot_sync(full, eq);
            if (eq) { int p = peq + __popc(b3 & ltm); if (p < KSEL) { sel_i[p] = v; sel_e[p] = e_s[v]; } }
            peq += __popc(b3);
        }
    }
    __syncthreads();

    if (tid < 32) {
        float m = 3.0e38f;
        for (int k = lane; k < KSEL; k += 32) m = fminf(m, sel_e[k]);
        for (int o = 16; o; o >>= 1) m = fminf(m, __shfl_xor_sync(full, m, o));
        if (lane == 0) s_min = m;
    }
    __syncthreads();
    float emin = s_min;
    float emax = __uint_as_float(kth);
    float denom = (emax - emin) + 1e-8f;
    if (tid < KSEL) sel_w[tid] = expf(-((sel_e[tid] - emin) / denom));
    __syncthreads();
    if (tid < 32) {
        float s = 0.f;
        for (int k = lane; k < KSEL; k += 32) s += sel_w[k];
        for (int o = 16; o; o >>= 1) s += __shfl_xor_sync(full, s, o);
        if (lane == 0) s_sum = s;
    }
    __syncthreads();

    if (tid < KSEL) {
        float w = sel_w[tid] / s_sum;
        sel_w[tid] = w;
        int v = sel_i[tid];
        float d0 = wrap01(q0 - __ldg(&pos[2 * v]));
        float d1 = wrap01(q1 - __ldg(&pos[2 * v + 1]));
#pragma unroll
        for (int j = 0; j < 16; j++) {
            float p = 6.283185307179586f * (d0 * bs[j] + d1 * bs[16 + j]);
            float sv, cv; __sincosf(p, &sv, &cv);
            kf_s[tid * 32 + j]      = sv;
            kf_s[tid * 32 + 16 + j] = cv;
        }
        d_g[(q * KSEL + tid) * JW + 32] = w;
        d_ind[q * KSEL + tid] = v;
    }
    __syncthreads();

#pragma unroll 1
    for (int rr = 0; rr < 13; rr++) {
        int k = wid + rr * 8;
        if (k < KSEL) {
            ull acc = 0;
            const ull* kp = (const ull*)&kf_s[k * 32];
#pragma unroll
            for (int t = 0; t < 16; t++) acc = fma2v(kp[t], wl[t], acc);
            float2 f = unpack2(acc);
            float a = f.x + f.y + b1r;
            float h = 0.5f * a * (1.0f + erff(a * 0.70710678118654752f));
            d_g[(q * KSEL + k) * JW + lane] = sel_w[k] * h;
        }
    }
}

// ============================================================
// K2a (R10/R14 version — best measured): block = (q, bt), 256 threads,
// 2-way k-split, thread tile 4c x 4j, 41.2 KB smem -> 5 blocks/SM.
// qbase selects the query chunk.
// ============================================================
#define GA_SMEM ((KSEL * GST + KSEL * C_IN) * 4)   // 41200 B

__global__ void __launch_bounds__(256, 5) k_gA(int qbase) {
    extern __shared__ __align__(16) float sm[];
    float* g_s = sm;                  // [103][36]
    float* xg  = sm + KSEL * GST;     // [103][64]; tail reused as reduction buf
    __shared__ int ind_s[KSEL];
    __shared__ float wred[8][C_IN];

    int bx = blockIdx.x, q = qbase + (bx >> 3), bt = bx & 7;
    int tid = threadIdx.x;

    if (tid < KSEL) ind_s[tid] = d_ind[q * KSEL + tid];
    {
        const float* gsrc = &d_g[q * KSEL * JW];
        for (int i = tid; i < KSEL * JW; i += 256) {
            int k = i / 33, j = i - k * 33;
            g_s[k * GST + j] = gsrc[i];
        }
    }
    __syncthreads();

    // gather: warp w loads rows w, w+8, ...; float2 per lane; w-column on the fly
    {
        int w = tid >> 5, lane = tid & 31;
        const float* xb = &d_xl[bt * V_N * C_IN];
        float2 wa = make_float2(0.f, 0.f);
        for (int r = w; r < KSEL; r += 8) {
            float2 v = __ldg((const float2*)&xb[ind_s[r] * C_IN + lane * 2]);
            *(float2*)&xg[r * C_IN + lane * 2] = v;
            float wr = g_s[r * GST + 32];
            wa.x += wr * v.x; wa.y += wr * v.y;
        }
        wred[w][lane * 2]     = wa.x;
        wred[w][lane * 2 + 1] = wa.y;
    }
    __syncthreads();

    int kh = tid >> 7;                 // k-half: 0 -> [0,52), 1 -> [52,103)
    int t  = tid & 127;
    int cg = t & 15, jg = t >> 4;      // 16 c-groups of 4; 8 j-groups of 4
    const float* xgp = &xg[cg * 4];
    const float* gsp = &g_s[jg * 4];
    int kbeg = kh ? 52 : 0;
    int kend = kh ? KSEL : 52;

    ull acc[4][2];
#pragma unroll
    for (int a = 0; a < 4; a++) { acc[a][0] = 0; acc[a][1] = 0; }

#pragma unroll 2
    for (int k = kbeg; k < kend; k++) {
        ulonglong2 x0 = *(const ulonglong2*)&xgp[k * C_IN];
        float4 g4 = *(const float4*)&gsp[k * GST];
        ull gp0 = pack2(g4.x, g4.x), gp1 = pack2(g4.y, g4.y);
        ull gp2 = pack2(g4.z, g4.z), gp3 = pack2(g4.w, g4.w);
        acc[0][0] = fma2v(x0.x, gp0, acc[0][0]); acc[0][1] = fma2v(x0.y, gp0, acc[0][1]);
        acc[1][0] = fma2v(x0.x, gp1, acc[1][0]); acc[1][1] = fma2v(x0.y, gp1, acc[1][1]);
        acc[2][0] = fma2v(x0.x, gp2, acc[2][0]); acc[2][1] = fma2v(x0.y, gp2, acc[2][1]);
        acc[3][0] = fma2v(x0.x, gp3, acc[3][0]); acc[3][1] = fma2v(x0.y, gp3, acc[3][1]);
    }

    __syncthreads();
    float* red = xg;                   // [128][20] (80B stride, 16B-aligned)
    if (kh == 1) {
        float* rp = &red[t * 20];
#pragma unroll
        for (int j2 = 0; j2 < 4; j2++)
            *(ulonglong2*)&rp[j2 * 4] = make_ulonglong2(acc[j2][0], acc[j2][1]);
    }
    __syncthreads();
    if (kh == 0) {
        const float* rp = &red[t * 20];
        int row = bt * Q_N + q;
        float* Ar = &d_A[row * M_TOT];
#pragma unroll
        for (int j2 = 0; j2 < 4; j2++) {
            float2 f0 = unpack2(acc[j2][0]), f1 = unpack2(acc[j2][1]);
            float4 p = *(const float4*)&rp[j2 * 4];
            *(float4*)&Ar[(jg * 4 + j2) * C_IN + cg * 4] =
                make_float4(f0.x + p.x, f0.y + p.y, f1.x + p.z, f1.y + p.w);
        }
        if (t < C_IN) {
            float a0 = 0.f;
#pragma unroll
            for (int rr = 0; rr < 8; rr++) a0 += wred[rr][t];
            Ar[32 * C_IN + t] = a0;
        }
    }
}

// ============================================================
// K2b: register-blocked GEMM on transposed A tile.
// grid = 64 row-tiles x 11 m-splits = 704 blocks (~4.8/SM).
// ============================================================
#define AST 66      // As_t row stride (even -> 8B-aligned pairs)

__global__ void __launch_bounds__(256) k_gB1() {
    __shared__ __align__(16) float As[64 * AST];   // [m][row] 16.9KB
    __shared__ __align__(16) float Wt[64 * 32];    // [m][d]    8KB
    int bx = blockIdx.x;
    int rt = bx & 63, ms = bx >> 6;                // 704 blocks = 11 x 64
    int tid = threadIdx.x;
    int rp = tid >> 3, dq = tid & 7;               // 32 row-pairs x 8 d-quads
    int r0 = rt * 64;
    int mbase0 = ms * 192;

    ull acc[4] = {0, 0, 0, 0};

    for (int st = 0; st < 3; st++) {
        int mb = mbase0 + st * 64;
        for (int i = tid; i < 4096; i += 256) {
            int row = i >> 6, m = i & 63;
            As[m * AST + row] = d_A[(r0 + row) * M_TOT + mb + m];
        }
        const float* wsrc = &d_W2e[mb * 32];
        for (int i = tid; i < 2048; i += 256) Wt[i] = wsrc[i];
        __syncthreads();

        const float* ap = &As[rp * 2];
        const float* wp = &Wt[dq * 4];
#pragma unroll 4
        for (int m = 0; m < 64; m++) {
            ull a = *(const ull*)&ap[m * AST];
            float4 w4 = *(const float4*)&wp[m * 32];
            acc[0] = fma2v(a, pack2(w4.x, w4.x), acc[0]);
            acc[1] = fma2v(a, pack2(w4.y, w4.y), acc[1]);
            acc[2] = fma2v(a, pack2(w4.z, w4.z), acc[2]);
            acc[3] = fma2v(a, pack2(w4.w, w4.w), acc[3]);
        }
        __syncthreads();
    }

    int row0 = r0 + rp * 2;
    float* pp = &d_part[(ms * 4096 + row0) * 32 + dq * 4];
#pragma unroll
    for (int j = 0; j < 4; j++) {
        float2 f = unpack2(acc[j]);
        pp[j]      = f.x;
        pp[32 + j] = f.y;
    }
}

__global__ void k_gB2(const float* __restrict__ bias, float* __restrict__ out) {
    int i = blockIdx.x * 256 + threadIdx.x;        // 131072 outputs
    if (i < BT_N * Q_N * 32) {
        float s = __ldg(&bias[i & 31]);
#pragma unroll
        for (int ms = 0; ms < NSPLIT; ms++)
            s += d_part[ms * 131072 + i];
        out[i] = s;
    }
}

// ============================================================
extern "C" void kernel_launch(void* const* d_in, const int* in_sizes, int n_in,
                              void* d_out, int out_size) {
    const float* x    = (const float*)d_in[0];
    const float* pos  = (const float*)d_in[1];
    const float* qpos = (const float*)d_in[2];
    const float* Wl   = (const float*)d_in[3];
    const float* bl   = (const float*)d_in[4];
    const float* Bm   = (const float*)d_in[5];
    const float* W1   = (const float*)d_in[6];
    const float* b1   = (const float*)d_in[7];
    const float* W2   = (const float*)d_in[8];
    const float* filt = (const float*)d_in[9];
    const float* bias = (const float*)d_in[10];
    float* out = (float*)d_out;

    static cudaStream_t s1 = nullptr, s2 = nullptr, s3 = nullptr;
    static cudaEvent_t evRoot = nullptr, evX = nullptr, evA = nullptr,
                       evB = nullptr, evGA = nullptr, evGB = nullptr;
    if (!s1) {
        cudaStreamCreateWithFlags(&s1, cudaStreamNonBlocking);
        cudaStreamCreateWithFlags(&s2, cudaStreamNonBlocking);
        cudaStreamCreateWithFlags(&s3, cudaStreamNonBlocking);
        cudaEventCreateWithFlags(&evRoot, cudaEventDisableTiming);
        cudaEventCreateWithFlags(&evX, cudaEventDisableTiming);
        cudaEventCreateWithFlags(&evA, cudaEventDisableTiming);
        cudaEventCreateWithFlags(&evB, cudaEventDisableTiming);
        cudaEventCreateWithFlags(&evGA, cudaEventDisableTiming);
        cudaEventCreateWithFlags(&evGB, cudaEventDisableTiming);
        cudaFuncSetAttribute(k_gA, cudaFuncAttributeMaxDynamicSharedMemorySize, GA_SMEM);
    }

    // fork root
    cudaEventRecord(evRoot, 0);
    cudaStreamWaitEvent(s1, evRoot, 0);
    cudaStreamWaitEvent(s2, evRoot, 0);
    cudaStreamWaitEvent(s3, evRoot, 0);

    // s1: xlin + w2e (independent of select)
    k_xlin <<<2048, 256, 0, s1>>>(x, Wl, bl);
    k_w2e  <<<264, 256, 0, s1>>>(W2, filt);
    cudaEventRecord(evX, s1);

    // main stream: selectA then selectB (chunks of 256 queries)
    k_select<<<Q_N / 2, 256>>>(pos, qpos, Bm, W1, b1, 0);
    cudaEventRecord(evA, 0);
    k_select<<<Q_N / 2, 256>>>(pos, qpos, Bm, W1, b1, Q_N / 2);
    cudaEventRecord(evB, 0);

    // s2: gA for first chunk (overlaps selectB)
    cudaStreamWaitEvent(s2, evA, 0);
    cudaStreamWaitEvent(s2, evX, 0);
    k_gA<<<(Q_N / 2) * BT_N, 256, GA_SMEM, s2>>>(0);
    cudaEventRecord(evGA, s2);

    // s3: gA for second chunk
    cudaStreamWaitEvent(s3, evB, 0);
    cudaStreamWaitEvent(s3, evX, 0);
    k_gA<<<(Q_N / 2) * BT_N, 256, GA_SMEM, s3>>>(Q_N / 2);
    cudaEventRecord(evGB, s3);

    // join on main stream, then gB
    cudaStreamWaitEvent(0, evGA, 0);
    cudaStreamWaitEvent(0, evGB, 0);
    k_gB1 <<<64 * NSPLIT, 256>>>();
    k_gB2 <<<512, 256>>>(bias, out);
}